// round 2
// baseline (speedup 1.0000x reference)
#include <cuda_runtime.h>
#include <cstdint>
#include <cstring>

#define THREADS 256
#define TE      128      // edges per tile
#define PADK    145      // per-edge-pair row stride (in float2/ull units)
#define KIN     144
#define HID     64
#define NEG     0.1f
#define LNEPS   1e-5f
#define HR_STR  68       // Hraw row stride in floats (16B-aligned rows)

typedef unsigned long long ull;

// smem layout (floats)
#define X2_F   (64 * PADK * 2)   // 18560  edge-pair interleaved X / H tile
#define W1_F   (KIN * HID)       // 9216
#define W2_F   (HID * HID)       // 4096
#define HR_F   (TE * HR_STR)     // 8704
#define VEC_F  512
#define SMEM_F (X2_F + W1_F + W2_F + HR_F + VEC_F)
#define SMEM_BYTES (SMEM_F * 4)

__device__ int g_is32;

// ---------------------------------------------------------------------------
// Detect whether edge_index is really int64 or silently-demoted int32.
// If int32, interpreting as int64 fuses two indices -> values >= 2^32.
__global__ void check_idx_kernel(const long long* __restrict__ idx, long long n,
                                 unsigned long long n_nodes) {
    __shared__ int bad;
    if (threadIdx.x == 0) bad = 0;
    __syncthreads();
    int local = 0;
    for (long long i = threadIdx.x; i < n; i += blockDim.x) {
        if ((unsigned long long)idx[i] >= n_nodes) local = 1;
    }
    if (local) bad = 1;
    __syncthreads();
    if (threadIdx.x == 0) g_is32 = bad;
}

// ---------------------------------------------------------------------------
__device__ __forceinline__ void fma2(ull& d, ull a, ull b) {
    asm("fma.rn.f32x2 %0, %1, %2, %0;" : "+l"(d) : "l"(a), "l"(b));
}
__device__ __forceinline__ ull dup2(float v) {
    ull r;
    asm("mov.b64 %0, {%1, %1};" : "=l"(r) : "f"(v));
    return r;
}

template<int K>
__device__ __forceinline__ void gemm_tile(const float* __restrict__ X2f,
                                          const float* __restrict__ Wd,
                                          ull acc[2][8], int p0, int c0) {
    const ull* xr0 = (const ull*)X2f + (size_t)p0 * PADK;
    const ull* xr1 = xr0 + PADK;
    const float* wr = Wd + c0;
    #pragma unroll 4
    for (int k = 0; k < K; k++) {
        ull x0 = xr0[k];
        ull x1 = xr1[k];
        const float* w = wr + (size_t)k * HID;
        float4 wa = *(const float4*)(w);
        float4 wb = *(const float4*)(w + 4);
        ull w0 = dup2(wa.x), w1 = dup2(wa.y), w2 = dup2(wa.z), w3 = dup2(wa.w);
        ull w4 = dup2(wb.x), w5 = dup2(wb.y), w6 = dup2(wb.z), w7 = dup2(wb.w);
        fma2(acc[0][0], x0, w0); fma2(acc[1][0], x1, w0);
        fma2(acc[0][1], x0, w1); fma2(acc[1][1], x1, w1);
        fma2(acc[0][2], x0, w2); fma2(acc[1][2], x1, w2);
        fma2(acc[0][3], x0, w3); fma2(acc[1][3], x1, w3);
        fma2(acc[0][4], x0, w4); fma2(acc[1][4], x1, w4);
        fma2(acc[0][5], x0, w5); fma2(acc[1][5], x1, w5);
        fma2(acc[0][6], x0, w6); fma2(acc[1][6], x1, w6);
        fma2(acc[0][7], x0, w7); fma2(acc[1][7], x1, w7);
    }
}

__device__ __forceinline__ void epilogue_store(ull acc[2][8], float* __restrict__ Hraw,
                                               const float* __restrict__ bias,
                                               int p0, int c0) {
    #pragma unroll
    for (int i = 0; i < 2; i++) {
        int e0 = (p0 + i) * 2;
        #pragma unroll
        for (int j = 0; j < 8; j++) {
            float2 f;
            memcpy(&f, &acc[i][j], 8);
            float bb = bias[c0 + j];
            Hraw[(size_t)e0 * HR_STR + c0 + j]       = f.x + bb;
            Hraw[(size_t)(e0 + 1) * HR_STR + c0 + j] = f.y + bb;
        }
    }
}

// ---------------------------------------------------------------------------
extern "C" __global__ void __launch_bounds__(THREADS, 1)
edge_mlp_kernel(const float* __restrict__ nodes,
                const void*  __restrict__ eidx,
                const float* __restrict__ eattr,
                const float* __restrict__ W1g, const float* __restrict__ b1g,
                const float* __restrict__ g1g, const float* __restrict__ be1g,
                const float* __restrict__ W2g, const float* __restrict__ b2g,
                const float* __restrict__ g2g, const float* __restrict__ be2g,
                const float* __restrict__ W3g, const float* __restrict__ b3g,
                float* __restrict__ out, long long E)
{
    extern __shared__ float sm[];
    float* X2f  = sm;
    float* Wd1  = X2f + X2_F;
    float* Wd2  = Wd1 + W1_F;
    float* Hraw = Wd2 + W2_F;
    float* vec  = Hraw + HR_F;
    float* b1s = vec;        float* g1s = vec + 64;  float* be1s = vec + 128;
    float* b2s = vec + 192;  float* g2s = vec + 256; float* be2s = vec + 320;
    float* W3s = vec + 384;

    const int tid = threadIdx.x;

    // stage weights once per block (L2-resident reads)
    for (int i = tid; i < W1_F / 4; i += THREADS)
        ((float4*)Wd1)[i] = ((const float4*)W1g)[i];
    for (int i = tid; i < W2_F / 4; i += THREADS)
        ((float4*)Wd2)[i] = ((const float4*)W2g)[i];
    if (tid < 64) {
        b1s[tid] = b1g[tid];  g1s[tid] = g1g[tid];  be1s[tid] = be1g[tid];
        b2s[tid] = b2g[tid];  g2s[tid] = g2g[tid];  be2s[tid] = be2g[tid];
        W3s[tid] = W3g[tid];
    }
    const float b3v = b3g[0];
    const int is32 = g_is32;
    __syncthreads();

    const long long ntiles = (E + TE - 1) / TE;
    const int cg = tid & 7, eg = tid >> 3;
    const int c0 = cg * 8, p0 = eg * 2;

    for (long long tile = blockIdx.x; tile < ntiles; tile += gridDim.x) {
        const long long Eb = tile * (long long)TE;

        // ---- stage X tile: 2 threads per edge (q=0: src+attr lo, q=1: dst+attr hi)
        {
            const int s = tid >> 1, q = tid & 1;
            long long e = Eb + s;
            if (e > E - 1) e = E - 1;
            long long row;
            if (is32) {
                const int* I = (const int*)eidx;
                row = (long long)I[q ? (E + e) : e];
            } else {
                const long long* I = (const long long*)eidx;
                row = I[q ? (E + e) : e];
            }
            const float4* rp = (const float4*)(nodes + row * 64);
            const int p = s >> 1, par = s & 1;
            float* xb = X2f + par;
            const int cbase = q * 64;
            #pragma unroll
            for (int m = 0; m < 16; m++) {
                float4 v = rp[m];
                int c = cbase + m * 4;
                size_t base = ((size_t)p * PADK + c) * 2;
                xb[base + 0] = v.x; xb[base + 2] = v.y;
                xb[base + 4] = v.z; xb[base + 6] = v.w;
            }
            const float4* ap = (const float4*)(eattr + e * 16);
            #pragma unroll
            for (int m = 0; m < 2; m++) {
                float4 v = ap[q * 2 + m];
                int c = 128 + (q * 2 + m) * 4;
                size_t base = ((size_t)p * PADK + c) * 2;
                xb[base + 0] = v.x; xb[base + 2] = v.y;
                xb[base + 4] = v.z; xb[base + 6] = v.w;
            }
        }
        __syncthreads();  // S1: X staged

        // ---- GEMM1: (128 x 144) @ (144 x 64)
        ull acc[2][8];
        #pragma unroll
        for (int i = 0; i < 2; i++)
            #pragma unroll
            for (int j = 0; j < 8; j++) acc[i][j] = 0ULL;
        gemm_tile<KIN>(X2f, Wd1, acc, p0, c0);
        epilogue_store(acc, Hraw, b1s, p0, c0);
        __syncthreads();  // S2: Hraw complete

        // ---- LN1 + leaky -> write back into X2 region as GEMM2 input
        if (tid < TE) {
            const float4* row = (const float4*)(Hraw + (size_t)tid * HR_STR);
            float s = 0.f, ss = 0.f;
            #pragma unroll
            for (int m = 0; m < 16; m++) {
                float4 v = row[m];
                s  += (v.x + v.y) + (v.z + v.w);
                ss += v.x * v.x + v.y * v.y + v.z * v.z + v.w * v.w;
            }
            float mu  = s * 0.015625f;
            float var = ss * 0.015625f - mu * mu;
            float rs  = rsqrtf(var + LNEPS);
            const int p = tid >> 1, par = tid & 1;
            float* dst = X2f + par;
            #pragma unroll
            for (int m = 0; m < 16; m++) {
                float4 v = row[m];
                int c = m * 4;
                float n0 = (v.x - mu) * rs * g1s[c + 0] + be1s[c + 0];
                float n1 = (v.y - mu) * rs * g1s[c + 1] + be1s[c + 1];
                float n2 = (v.z - mu) * rs * g1s[c + 2] + be1s[c + 2];
                float n3 = (v.w - mu) * rs * g1s[c + 3] + be1s[c + 3];
                n0 = fmaxf(n0, NEG * n0); n1 = fmaxf(n1, NEG * n1);
                n2 = fmaxf(n2, NEG * n2); n3 = fmaxf(n3, NEG * n3);
                size_t base = ((size_t)p * PADK + c) * 2;
                dst[base + 0] = n0; dst[base + 2] = n1;
                dst[base + 4] = n2; dst[base + 6] = n3;
            }
        }
        __syncthreads();  // S3: H staged for GEMM2

        // ---- GEMM2: (128 x 64) @ (64 x 64)
        #pragma unroll
        for (int i = 0; i < 2; i++)
            #pragma unroll
            for (int j = 0; j < 8; j++) acc[i][j] = 0ULL;
        gemm_tile<HID>(X2f, Wd2, acc, p0, c0);
        epilogue_store(acc, Hraw, b2s, p0, c0);
        __syncthreads();  // S4: Hraw complete

        // ---- LN2 + leaky + dot(W3) + b3 -> global out
        if (tid < TE) {
            const float4* row = (const float4*)(Hraw + (size_t)tid * HR_STR);
            float s = 0.f, ss = 0.f;
            #pragma unroll
            for (int m = 0; m < 16; m++) {
                float4 v = row[m];
                s  += (v.x + v.y) + (v.z + v.w);
                ss += v.x * v.x + v.y * v.y + v.z * v.z + v.w * v.w;
            }
            float mu  = s * 0.015625f;
            float var = ss * 0.015625f - mu * mu;
            float rs  = rsqrtf(var + LNEPS);
            float accO = 0.f;
            #pragma unroll
            for (int m = 0; m < 16; m++) {
                float4 v = row[m];
                int c = m * 4;
                float n0 = (v.x - mu) * rs * g2s[c + 0] + be2s[c + 0];
                float n1 = (v.y - mu) * rs * g2s[c + 1] + be2s[c + 1];
                float n2 = (v.z - mu) * rs * g2s[c + 2] + be2s[c + 2];
                float n3 = (v.w - mu) * rs * g2s[c + 3] + be2s[c + 3];
                n0 = fmaxf(n0, NEG * n0); n1 = fmaxf(n1, NEG * n1);
                n2 = fmaxf(n2, NEG * n2); n3 = fmaxf(n3, NEG * n3);
                accO += n0 * W3s[c + 0] + n1 * W3s[c + 1]
                      + n2 * W3s[c + 2] + n3 * W3s[c + 3];
            }
            long long e = Eb + tid;
            if (e < E) out[e] = accO + b3v;
        }
        // next iteration's staging (X2 writes) is fenced by S1; LN2 touches
        // only Hraw + gmem, and every thread finishes LN2 before its own
        // staging, so S1 also covers the Hraw reuse.
    }
}

// ---------------------------------------------------------------------------
extern "C" void kernel_launch(void* const* d_in, const int* in_sizes, int n_in,
                              void* d_out, int out_size) {
    const float* nodes = (const float*)d_in[0];
    const void*  eidx  = d_in[1];
    const float* eattr = (const float*)d_in[2];
    const float* W1 = (const float*)d_in[3];
    const float* b1 = (const float*)d_in[4];
    const float* g1 = (const float*)d_in[5];
    const float* be1 = (const float*)d_in[6];
    const float* W2 = (const float*)d_in[7];
    const float* b2 = (const float*)d_in[8];
    const float* g2 = (const float*)d_in[9];
    const float* be2 = (const float*)d_in[10];
    const float* W3 = (const float*)d_in[11];
    const float* b3 = (const float*)d_in[12];
    float* out = (float*)d_out;

    const long long E = (long long)in_sizes[2] / 16;          // edge_attr: (E,16)
    const unsigned long long n_nodes = (unsigned long long)in_sizes[0] / 64;
    if (E <= 0) return;

    cudaFuncSetAttribute(edge_mlp_kernel,
                         cudaFuncAttributeMaxDynamicSharedMemorySize, SMEM_BYTES);

    int nsm = 148;
    cudaDeviceGetAttribute(&nsm, cudaDevAttrMultiProcessorCount, 0);
    if (nsm <= 0) nsm = 148;

    long long ncheck = E < 2048 ? E : 2048;
    check_idx_kernel<<<1, 256>>>((const long long*)eidx, ncheck, n_nodes);

    long long ntiles = (E + TE - 1) / TE;
    int grid = (ntiles < (long long)nsm) ? (int)ntiles : nsm;
    edge_mlp_kernel<<<grid, THREADS, SMEM_BYTES>>>(
        nodes, eidx, eattr, W1, b1, g1, be1, W2, b2, g2, be2, W3, b3, out, E);
}

// round 7
// speedup vs baseline: 1.2821x; 1.2821x over previous
#include <cuda_runtime.h>
#include <cstdint>

#define THREADS 256
#define TE      256       // edges per tile
#define NPAIR   128       // edge pairs per tile
#define PADK    146       // per-pair k-stride in ull units (even -> 16B alignment)
#define KIN     144
#define HID     64
#define NEG     0.1f
#define LNEPS   1e-5f

typedef unsigned long long ull;

// smem layout (floats)
#define X2_U   (NPAIR * PADK)            // 18688 ull = 37376 floats
#define W1_F   (KIN * HID)               // 9216
#define W2_F   (HID * HID)               // 4096
#define VEC_F  512
#define SMEM_F (2 * X2_U + W1_F + W2_F + VEC_F)   // 51200 floats
#define SMEM_BYTES (SMEM_F * 4)                   // 204800 B

__device__ int g_is32;

// ---------------------------------------------------------------------------
// Detect whether edge_index is really int64 or silently-demoted int32.
__global__ void check_idx_kernel(const long long* __restrict__ idx, long long n,
                                 unsigned long long n_nodes) {
    __shared__ int bad;
    if (threadIdx.x == 0) bad = 0;
    __syncthreads();
    int local = 0;
    for (long long i = threadIdx.x; i < n; i += blockDim.x) {
        if ((unsigned long long)idx[i] >= n_nodes) local = 1;
    }
    if (local) bad = 1;
    __syncthreads();
    if (threadIdx.x == 0) g_is32 = bad;
}

// ---------------------------------------------------------------------------
__device__ __forceinline__ void fma2(ull& d, ull a, ull b) {
    asm("fma.rn.f32x2 %0, %1, %2, %0;" : "+l"(d) : "l"(a), "l"(b));
}
__device__ __forceinline__ void add2(ull& d, ull b) {
    asm("add.rn.f32x2 %0, %0, %1;" : "+l"(d) : "l"(b));
}
__device__ __forceinline__ ull dup2(float v) {
    ull r;
    asm("mov.b64 %0, {%1, %1};" : "=l"(r) : "f"(v));
    return r;
}

// ---------------------------------------------------------------------------
// GEMM micro-tile: 4 edge-pairs (8 edges) x 8 cols per thread.
// Weights laid out per k-row as [j0..3 of cg0..7][j4..7 of cg0..7] so a
// quarter-warp's LDS.128 covers a contiguous, conflict-free 128B.
template<int K>
__device__ __forceinline__ void gemm_tile(const ull* __restrict__ X2u,
                                          const float* __restrict__ Wd,
                                          ull acc[4][8], int p0, int cg4) {
    const ull* xr = X2u + (size_t)p0 * PADK;
    #pragma unroll 2
    for (int k = 0; k < K; k += 2) {
        ulonglong2 xa = *(const ulonglong2*)(xr + k);
        ulonglong2 xb = *(const ulonglong2*)(xr + PADK + k);
        ulonglong2 xc = *(const ulonglong2*)(xr + 2 * PADK + k);
        ulonglong2 xd = *(const ulonglong2*)(xr + 3 * PADK + k);
        const float* w = Wd + (size_t)k * 64 + cg4;
        float4 wa0 = *(const float4*)(w);
        float4 wb0 = *(const float4*)(w + 32);
        float4 wa1 = *(const float4*)(w + 64);
        float4 wb1 = *(const float4*)(w + 96);
        {
            ull w0 = dup2(wa0.x), w1 = dup2(wa0.y), w2 = dup2(wa0.z), w3 = dup2(wa0.w);
            ull w4 = dup2(wb0.x), w5 = dup2(wb0.y), w6 = dup2(wb0.z), w7 = dup2(wb0.w);
            fma2(acc[0][0], xa.x, w0); fma2(acc[1][0], xb.x, w0);
            fma2(acc[2][0], xc.x, w0); fma2(acc[3][0], xd.x, w0);
            fma2(acc[0][1], xa.x, w1); fma2(acc[1][1], xb.x, w1);
            fma2(acc[2][1], xc.x, w1); fma2(acc[3][1], xd.x, w1);
            fma2(acc[0][2], xa.x, w2); fma2(acc[1][2], xb.x, w2);
            fma2(acc[2][2], xc.x, w2); fma2(acc[3][2], xd.x, w2);
            fma2(acc[0][3], xa.x, w3); fma2(acc[1][3], xb.x, w3);
            fma2(acc[2][3], xc.x, w3); fma2(acc[3][3], xd.x, w3);
            fma2(acc[0][4], xa.x, w4); fma2(acc[1][4], xb.x, w4);
            fma2(acc[2][4], xc.x, w4); fma2(acc[3][4], xd.x, w4);
            fma2(acc[0][5], xa.x, w5); fma2(acc[1][5], xb.x, w5);
            fma2(acc[2][5], xc.x, w5); fma2(acc[3][5], xd.x, w5);
            fma2(acc[0][6], xa.x, w6); fma2(acc[1][6], xb.x, w6);
            fma2(acc[2][6], xc.x, w6); fma2(acc[3][6], xd.x, w6);
            fma2(acc[0][7], xa.x, w7); fma2(acc[1][7], xb.x, w7);
            fma2(acc[2][7], xc.x, w7); fma2(acc[3][7], xd.x, w7);
        }
        {
            ull w0 = dup2(wa1.x), w1 = dup2(wa1.y), w2 = dup2(wa1.z), w3 = dup2(wa1.w);
            ull w4 = dup2(wb1.x), w5 = dup2(wb1.y), w6 = dup2(wb1.z), w7 = dup2(wb1.w);
            fma2(acc[0][0], xa.y, w0); fma2(acc[1][0], xb.y, w0);
            fma2(acc[2][0], xc.y, w0); fma2(acc[3][0], xd.y, w0);
            fma2(acc[0][1], xa.y, w1); fma2(acc[1][1], xb.y, w1);
            fma2(acc[2][1], xc.y, w1); fma2(acc[3][1], xd.y, w1);
            fma2(acc[0][2], xa.y, w2); fma2(acc[1][2], xb.y, w2);
            fma2(acc[2][2], xc.y, w2); fma2(acc[3][2], xd.y, w2);
            fma2(acc[0][3], xa.y, w3); fma2(acc[1][3], xb.y, w3);
            fma2(acc[2][3], xc.y, w3); fma2(acc[3][3], xd.y, w3);
            fma2(acc[0][4], xa.y, w4); fma2(acc[1][4], xb.y, w4);
            fma2(acc[2][4], xc.y, w4); fma2(acc[3][4], xd.y, w4);
            fma2(acc[0][5], xa.y, w5); fma2(acc[1][5], xb.y, w5);
            fma2(acc[2][5], xc.y, w5); fma2(acc[3][5], xd.y, w5);
            fma2(acc[0][6], xa.y, w6); fma2(acc[1][6], xb.y, w6);
            fma2(acc[2][6], xc.y, w6); fma2(acc[3][6], xd.y, w6);
            fma2(acc[0][7], xa.y, w7); fma2(acc[1][7], xb.y, w7);
            fma2(acc[2][7], xc.y, w7); fma2(acc[3][7], xd.y, w7);
        }
    }
}

// Epilogue: add bias (packed) and store the f32x2 accumulator pair directly
// into the interleaved tile at k-slot = column. Zero unpacking.
__device__ __forceinline__ void epi_store(ull acc[4][8], ull* __restrict__ X2u,
                                          const float* __restrict__ bias,
                                          int p0, int c0) {
    #pragma unroll
    for (int j = 0; j < 8; j++) {
        ull b = dup2(bias[c0 + j]);
        #pragma unroll
        for (int i = 0; i < 4; i++) {
            add2(acc[i][j], b);
            X2u[(size_t)(p0 + i) * PADK + (c0 + j)] = acc[i][j];
        }
    }
}

// ---------------------------------------------------------------------------
extern "C" __global__ void __launch_bounds__(THREADS, 1)
edge_mlp_kernel(const float* __restrict__ nodes,
                const void*  __restrict__ eidx,
                const float* __restrict__ eattr,
                const float* __restrict__ W1g, const float* __restrict__ b1g,
                const float* __restrict__ g1g, const float* __restrict__ be1g,
                const float* __restrict__ W2g, const float* __restrict__ b2g,
                const float* __restrict__ g2g, const float* __restrict__ be2g,
                const float* __restrict__ W3g, const float* __restrict__ b3g,
                float* __restrict__ out, long long E)
{
    extern __shared__ float sm[];
    ull*   X2u = (ull*)sm;
    float* X2f = sm;
    float* Wd1 = sm + 2 * X2_U;
    float* Wd2 = Wd1 + W1_F;
    float* vec = Wd2 + W2_F;
    float* b1s = vec;        float* g1s = vec + 64;  float* be1s = vec + 128;
    float* b2s = vec + 192;  float* g2s = vec + 256; float* be2s = vec + 320;
    float* W3s = vec + 384;

    const int tid = threadIdx.x;

    // Stage weights with per-row swizzle:
    // element (k, c=cg*8+j) -> k*64 + (j&4 ? 32 : 0) + cg*4 + (j&3)
    for (int i = tid; i < W1_F; i += THREADS) {
        int k = i >> 6, c = i & 63;
        int cg = c >> 3, j = c & 7;
        Wd1[k * 64 + ((j & 4) ? 32 : 0) + cg * 4 + (j & 3)] = W1g[i];
    }
    for (int i = tid; i < W2_F; i += THREADS) {
        int k = i >> 6, c = i & 63;
        int cg = c >> 3, j = c & 7;
        Wd2[k * 64 + ((j & 4) ? 32 : 0) + cg * 4 + (j & 3)] = W2g[i];
    }
    if (tid < 64) {
        b1s[tid] = b1g[tid];  g1s[tid] = g1g[tid];  be1s[tid] = be1g[tid];
        b2s[tid] = b2g[tid];  g2s[tid] = g2g[tid];  be2s[tid] = be2g[tid];
        W3s[tid] = W3g[tid];
    }
    const float b3v = b3g[0];
    const int is32 = g_is32;
    __syncthreads();

    const long long ntiles = (E + TE - 1) / TE;
    const int cg = tid & 7, eg = tid >> 3;
    const int c0 = cg * 8, cg4 = cg * 4, p0 = eg * 4;
    const int lp = tid >> 1, lpar = tid & 1;   // LN / staging mapping

    for (long long tile = blockIdx.x; tile < ntiles; tile += gridDim.x) {
        const long long Eb = tile * (long long)TE;

        // ---- stage X tile: one thread per edge (interleaved pair layout)
        {
            long long e = Eb + tid;
            if (e > E - 1) e = E - 1;
            long long r0, r1;
            if (is32) {
                const int* I = (const int*)eidx;
                r0 = (long long)I[e];  r1 = (long long)I[E + e];
            } else {
                const long long* I = (const long long*)eidx;
                r0 = I[e];  r1 = I[E + e];
            }
            float* xb = X2f + lpar;
            const float4* sp = (const float4*)(nodes + r0 * 64);
            #pragma unroll
            for (int m = 0; m < 16; m++) {
                float4 v = sp[m];
                size_t b = ((size_t)lp * PADK + m * 4) * 2;
                xb[b] = v.x; xb[b + 2] = v.y; xb[b + 4] = v.z; xb[b + 6] = v.w;
            }
            const float4* dp = (const float4*)(nodes + r1 * 64);
            #pragma unroll
            for (int m = 0; m < 16; m++) {
                float4 v = dp[m];
                size_t b = ((size_t)lp * PADK + 64 + m * 4) * 2;
                xb[b] = v.x; xb[b + 2] = v.y; xb[b + 4] = v.z; xb[b + 6] = v.w;
            }
            const float4* ap = (const float4*)(eattr + e * 16);
            #pragma unroll
            for (int m = 0; m < 4; m++) {
                float4 v = ap[m];
                size_t b = ((size_t)lp * PADK + 128 + m * 4) * 2;
                xb[b] = v.x; xb[b + 2] = v.y; xb[b + 4] = v.z; xb[b + 6] = v.w;
            }
        }
        __syncthreads();  // S1: X staged

        // ---- GEMM1: (256 x 144) @ (144 x 64)
        ull acc[4][8];
        #pragma unroll
        for (int i = 0; i < 4; i++)
            #pragma unroll
            for (int j = 0; j < 8; j++) acc[i][j] = 0ULL;
        gemm_tile<KIN>(X2u, Wd1, acc, p0, cg4);
        __syncthreads();  // S2: all X reads done (epi overwrites k-slots 0..63)
        epi_store(acc, X2u, b1s, p0, c0);
        __syncthreads();  // S3: raw H complete

        // ---- LN1 + leaky, in place (one thread per edge)
        // float4 m covers k-slots 2m, 2m+1 (both parities); own parity only.
        {
            const float4* rp = (const float4*)(X2f + (size_t)lp * PADK * 2);
            float s = 0.f, ss = 0.f;
            #pragma unroll
            for (int m = 0; m < 32; m++) {
                float4 v = rp[m];
                float a = lpar ? v.y : v.x;     // k = 2m
                float b = lpar ? v.w : v.z;     // k = 2m+1
                s += a + b;  ss += a * a + b * b;
            }
            float mu  = s * 0.015625f;
            float var = ss * 0.015625f - mu * mu;
            float rs  = rsqrtf(var + LNEPS);
            #pragma unroll
            for (int m = 0; m < 32; m++) {
                float4 v = rp[m];
                float a = lpar ? v.y : v.x;
                float b = lpar ? v.w : v.z;
                int k0 = 2 * m;
                float na = (a - mu) * rs * g1s[k0] + be1s[k0];
                float nb = (b - mu) * rs * g1s[k0 + 1] + be1s[k0 + 1];
                na = fmaxf(na, NEG * na);  nb = fmaxf(nb, NEG * nb);
                size_t bidx = ((size_t)lp * PADK + k0) * 2 + lpar;
                X2f[bidx]     = na;
                X2f[bidx + 2] = nb;
            }
        }
        __syncthreads();  // S4: H normalized, ready for GEMM2

        // ---- GEMM2: (256 x 64) @ (64 x 64)
        #pragma unroll
        for (int i = 0; i < 4; i++)
            #pragma unroll
            for (int j = 0; j < 8; j++) acc[i][j] = 0ULL;
        gemm_tile<HID>(X2u, Wd2, acc, p0, cg4);
        __syncthreads();  // S5: all H reads done
        epi_store(acc, X2u, b2s, p0, c0);
        __syncthreads();  // S6: raw H2 complete

        // ---- LN2 + leaky + dot(W3) + b3 -> global out
        {
            const float4* rp = (const float4*)(X2f + (size_t)lp * PADK * 2);
            float s = 0.f, ss = 0.f;
            #pragma unroll
            for (int m = 0; m < 32; m++) {
                float4 v = rp[m];
                float a = lpar ? v.y : v.x;
                float b = lpar ? v.w : v.z;
                s += a + b;  ss += a * a + b * b;
            }
            float mu  = s * 0.015625f;
            float var = ss * 0.015625f - mu * mu;
            float rs  = rsqrtf(var + LNEPS);
            float accO = 0.f;
            #pragma unroll
            for (int m = 0; m < 32; m++) {
                float4 v = rp[m];
                float a = lpar ? v.y : v.x;
                float b = lpar ? v.w : v.z;
                int k0 = 2 * m;
                float na = (a - mu) * rs * g2s[k0] + be2s[k0];
                float nb = (b - mu) * rs * g2s[k0 + 1] + be2s[k0 + 1];
                na = fmaxf(na, NEG * na);  nb = fmaxf(nb, NEG * nb);
                accO += na * W3s[k0] + nb * W3s[k0 + 1];
            }
            long long e = Eb + tid;
            if (e < E) out[e] = accO + b3v;
        }
        __syncthreads();  // S7: LN2 reads done before next tile's staging
    }
}

// ---------------------------------------------------------------------------
extern "C" void kernel_launch(void* const* d_in, const int* in_sizes, int n_in,
                              void* d_out, int out_size) {
    const float* nodes = (const float*)d_in[0];
    const void*  eidx  = d_in[1];
    const float* eattr = (const float*)d_in[2];
    const float* W1 = (const float*)d_in[3];
    const float* b1 = (const float*)d_in[4];
    const float* g1 = (const float*)d_in[5];
    const float* be1 = (const float*)d_in[6];
    const float* W2 = (const float*)d_in[7];
    const float* b2 = (const float*)d_in[8];
    const float* g2 = (const float*)d_in[9];
    const float* be2 = (const float*)d_in[10];
    const float* W3 = (const float*)d_in[11];
    const float* b3 = (const float*)d_in[12];
    float* out = (float*)d_out;

    const long long E = (long long)in_sizes[2] / 16;
    const unsigned long long n_nodes = (unsigned long long)in_sizes[0] / 64;
    if (E <= 0) return;

    cudaFuncSetAttribute(edge_mlp_kernel,
                         cudaFuncAttributeMaxDynamicSharedMemorySize, SMEM_BYTES);

    int nsm = 148;
    cudaDeviceGetAttribute(&nsm, cudaDevAttrMultiProcessorCount, 0);
    if (nsm <= 0) nsm = 148;

    long long ncheck = E < 2048 ? E : 2048;
    check_idx_kernel<<<1, 256>>>((const long long*)eidx, ncheck, n_nodes);

    long long ntiles = (E + TE - 1) / TE;
    int grid = (ntiles < (long long)nsm) ? (int)ntiles : nsm;
    edge_mlp_kernel<<<grid, THREADS, SMEM_BYTES>>>(
        nodes, eidx, eattr, W1, b1, g1, be1, W2, b2, g2, be2, W3, b3, out, E);
}